// round 3
// baseline (speedup 1.0000x reference)
#include <cuda_runtime.h>
#include <math.h>

// Problem dims (fixed by the reference setup)
#define NB 4096
#define NT 512
#define NS 6
#define NF 12
#define STRIDE (NB * NS)   // floats per time-slice in [t][b][s] layout = 24576

// Scratch. emis: [t][b][s] with 8 slack slices for unguarded prefetch.
__device__ float    g_emis[(NT + 8) * NB * NS];
__device__ unsigned g_bp[NT * NB];        // packed backpointers, rows 1..511 used
__device__ int      g_last[NB];           // argmax state at t=511
__device__ float    g_logtrans[NS * NS];  // [p][s]
__device__ float    g_loginit[NS];
__device__ float    g_epar[2 * NS * NF + 2 * NS];  // inv2[72], mu*inv2[72], c[6], logdet[6]

// ---------------------------------------------------------------------------
// K0: tiny parameter precompute
// ---------------------------------------------------------------------------
__global__ void k_setup(const float* __restrict__ trans,
                        const float* __restrict__ init,
                        const float* __restrict__ means,
                        const float* __restrict__ logsc)
{
    if (threadIdx.x != 0 || blockIdx.x != 0) return;

    for (int p = 0; p < NS; p++) {
        float m = trans[p * NS];
        for (int s = 1; s < NS; s++) m = fmaxf(m, trans[p * NS + s]);
        float sum = 0.f;
        for (int s = 0; s < NS; s++) sum += expf(trans[p * NS + s] - m);
        for (int s = 0; s < NS; s++)
            g_logtrans[p * NS + s] = logf(expf(trans[p * NS + s] - m) / sum + 1e-8f);
    }
    {
        float m = init[0];
        for (int s = 1; s < NS; s++) m = fmaxf(m, init[s]);
        float sum = 0.f;
        for (int s = 0; s < NS; s++) sum += expf(init[s] - m);
        for (int s = 0; s < NS; s++)
            g_loginit[s] = logf(expf(init[s] - m) / sum + 1e-8f);
    }
    for (int s = 0; s < NS; s++) {
        float c = 0.f, ld = 0.f;
        for (int f = 0; f < NF; f++) {
            float x    = logsc[s * NF + f];
            float sc   = log1pf(expf(x)) + 1e-6f;
            float den  = sc + 1e-6f;
            float inv2 = 1.0f / (den * den);
            float mu   = means[s * NF + f];
            g_epar[s * NF + f]           = inv2;
            g_epar[NS * NF + s * NF + f] = mu * inv2;
            c  += mu * mu * inv2;
            ld += logf(sc);
        }
        g_epar[2 * NS * NF + s]      = c;
        g_epar[2 * NS * NF + NS + s] = ld;
    }
}

// ---------------------------------------------------------------------------
// K1: emission logp. 32b x 8t tile; coalesced obs reads (streaming, evict-
// first so emis/bp stay in L2) and coalesced [t][b][s] writes via shared tile.
// ---------------------------------------------------------------------------
#define TILE_PAD 196

__global__ void k_emis(const float* __restrict__ obs)
{
    __shared__ float sp[156];
    __shared__ float tile[8 * TILE_PAD];

    int tid = threadIdx.x;
    if (tid < 156) sp[tid] = g_epar[tid];
    __syncthreads();

    int tt = tid & 7, bb = tid >> 3;
    int t = blockIdx.x * 8 + tt;
    int b = blockIdx.y * 32 + bb;

    const float4* op = (const float4*)(obs + ((size_t)b * NT + t) * NF);
    float4 o0 = __ldcs(op), o1 = __ldcs(op + 1), o2v = __ldcs(op + 2);
    float o[12] = { o0.x, o0.y, o0.z, o0.w, o1.x, o1.y, o1.z, o1.w,
                    o2v.x, o2v.y, o2v.z, o2v.w };
    float osq[12];
#pragma unroll
    for (int f = 0; f < 12; f++) osq[f] = o[f] * o[f];

#pragma unroll
    for (int s = 0; s < NS; s++) {
        float a1 = 0.f, a2 = 0.f;
#pragma unroll
        for (int f = 0; f < 12; f++) {
            a1 = fmaf(osq[f], sp[s * 12 + f], a1);
            a2 = fmaf(o[f],   sp[72 + s * 12 + f], a2);
        }
        float e = -0.5f * (a1 - 2.f * a2 + sp[144 + s]) - sp[150 + s];
        tile[tt * TILE_PAD + bb * 6 + s] = e;
    }
    __syncthreads();

    size_t base = (size_t)(blockIdx.x * 8) * STRIDE + (size_t)blockIdx.y * 32 * NS;
#pragma unroll
    for (int k = 0; k < 6; k++) {
        int idx = k * 256 + tid;
        int tt2 = idx / 192;
        int r   = idx - tt2 * 192;
        g_emis[base + (size_t)tt2 * STRIDE + r] = tile[tt2 * TILE_PAD + r];
    }
}

// ---------------------------------------------------------------------------
// K2: forward Viterbi with packed backpointers. 1 thread/batch. Per step:
// 3 prefetch LDG.64 (depth-8 ring, streaming), 36 FADD, argmax ladder,
// 1 STG.32 (packed bp, coalesced). v stays in registers — NO v store.
// Final score + argmax state computed in-register at the end.
// ---------------------------------------------------------------------------
__global__ void k_fwd(float* __restrict__ out, int write_score, int score_off)
{
    int b = blockIdx.x * 32 + threadIdx.x;

    float lt[36];
#pragma unroll
    for (int i = 0; i < 36; i++) lt[i] = g_logtrans[i];

    const float* p = g_emis + (size_t)b * NS;

    float v[6];
#pragma unroll
    for (int s = 0; s < 6; s++) v[s] = g_loginit[s] + p[s];

    // prefetch ring: slot (t-1)&7 holds e(t)
    float eb[8][6];
#pragma unroll
    for (int k = 0; k < 8; k++) {
        const float2* q = (const float2*)(p + (size_t)(1 + k) * STRIDE);
        float2 a = __ldcs(q), bq = __ldcs(q + 1), c = __ldcs(q + 2);
        eb[k][0] = a.x; eb[k][1] = a.y; eb[k][2] = bq.x;
        eb[k][3] = bq.y; eb[k][4] = c.x; eb[k][5] = c.y;
    }

    unsigned* bprow = g_bp + b;

    for (int tb = 1; tb < 512; tb += 8) {
#pragma unroll
        for (int u = 0; u < 8; u++) {
            int t = tb + u;
            if (t < 512) {
                float e[6];
#pragma unroll
                for (int s = 0; s < 6; s++) e[s] = eb[u][s];
                // prefetch e(t+8); may land in zero slack (never consumed)
                {
                    const float2* q = (const float2*)(p + (size_t)(t + 8) * STRIDE);
                    float2 a = __ldcs(q), bq = __ldcs(q + 1), c = __ldcs(q + 2);
                    eb[u][0] = a.x; eb[u][1] = a.y; eb[u][2] = bq.x;
                    eb[u][3] = bq.y; eb[u][4] = c.x; eb[u][5] = c.y;
                }
                float nv[6];
                unsigned pk = 0;
#pragma unroll
                for (int s = 0; s < 6; s++) {
                    float m = v[0] + lt[s];
                    int idx = 0;
#pragma unroll
                    for (int pp = 1; pp < 6; pp++) {
                        float c2 = v[pp] + lt[pp * 6 + s];
                        if (c2 > m) { m = c2; idx = pp; }   // first-argmax (strict >)
                    }
                    nv[s] = m + e[s];
                    pk |= (unsigned)idx << (4 * s);
                }
#pragma unroll
                for (int s = 0; s < 6; s++) v[s] = nv[s];
                bprow[(size_t)t * NB] = pk;
            }
        }
    }

    // final state / score
    float m = v[0]; int idx = 0;
#pragma unroll
    for (int s = 1; s < 6; s++) if (v[s] > m) { m = v[s]; idx = s; }
    g_last[b] = idx;
    if (write_score) out[score_off + b] = m;
}

// ---------------------------------------------------------------------------
// K3: backtrace over packed backpointers. Per step: 1 prefetched LDG.32
// (128B/warp coalesced, L2-resident) + SHF/AND chain (~12 cyc). Path staged
// in 32x33 shared tile, flushed as coalesced rows every 32 steps.
// ---------------------------------------------------------------------------
__global__ void k_bwd(float* __restrict__ out, int write_path)
{
    __shared__ float tile[32 * 33];

    int lane = threadIdx.x;
    int b0 = blockIdx.x * 32;
    int b  = b0 + lane;

    int cur = g_last[b];
    const unsigned* bprow = g_bp + b;

    // prefetch ring depth 16: slot t&15 holds bp row t
    unsigned rb[16];
#pragma unroll
    for (int k = 0; k < 16; k++) {
        int t = 511 - k;
        rb[t & 15] = __ldg(bprow + (size_t)t * NB);
    }

#pragma unroll 4
    for (int t = 511; t >= 1; t--) {
        tile[lane * 33 + (t & 31)] = (float)cur;   // path[t]
        unsigned pk = rb[t & 15];
        if (t - 16 >= 1)
            rb[t & 15] = __ldg(bprow + (size_t)(t - 16) * NB);
        cur = (pk >> (cur * 4)) & 7;               // path[t-1]
        if ((t & 31) == 0) {                       // tile holds path[t .. t+31]
            __syncwarp();
            if (write_path) {
                for (int r = 0; r < 32; r++)
                    out[(size_t)(b0 + r) * NT + t + lane] = tile[r * 33 + lane];
            }
            __syncwarp();
        }
    }

    tile[lane * 33] = (float)cur;                  // path[0]
    __syncwarp();
    if (write_path) {
        for (int r = 0; r < 32; r++)
            out[(size_t)(b0 + r) * NT + lane] = tile[r * 33 + lane];
    }
}

// ---------------------------------------------------------------------------
extern "C" void kernel_launch(void* const* d_in, const int* in_sizes, int n_in,
                              void* d_out, int out_size)
{
    (void)in_sizes; (void)n_in;
    const float* obs  = (const float*)d_in[0];
    const float* tr   = (const float*)d_in[1];
    const float* ini  = (const float*)d_in[2];
    const float* mu   = (const float*)d_in[3];
    const float* lsc  = (const float*)d_in[4];
    float* out = (float*)d_out;

    const int PT = NB * NT;
    int write_path = 0, write_score = 0, score_off = 0;
    if (out_size >= PT + NB)      { write_path = 1; write_score = 1; score_off = PT; }
    else if (out_size >= PT)      { write_path = 1; }
    else                          { write_score = 1; score_off = 0; }

    k_setup<<<1, 32>>>(tr, ini, mu, lsc);
    k_emis<<<dim3(NT / 8, NB / 32), 256>>>(obs);
    k_fwd<<<NB / 32, 32>>>(out, write_score, score_off);
    k_bwd<<<NB / 32, 32>>>(out, write_path);
}

// round 5
// speedup vs baseline: 1.5470x; 1.5470x over previous
#include <cuda_runtime.h>
#include <math.h>

// Problem dims (fixed by the reference setup)
#define NB 4096
#define NT 512
#define NS 6
#define NF 12
#define STRIDE (NB * NS)   // floats per time-slice in [t][b][s] layout = 24576

// Scratch buffers (distinct symbols -> no aliasing between read/write streams)
__device__ float    g_emis[(NT + 8) * NB * NS];   // [t][b][s], 8 slack slices for prefetch
__device__ float    g_v[NT * NB * NS];            // Viterbi values, [t][b][s]
__device__ unsigned g_bp[NT * NB];                // packed backpointers, rows 1..511 used
__device__ int      g_last[NB];                   // argmax state at t=511
__device__ float    g_logtrans[NS * NS];          // [p][s]
__device__ float    g_loginit[NS];
__device__ float    g_epar[2 * NS * NF + 2 * NS]; // inv2[72], mu*inv2[72], c[6], logdet[6]

// ---------------------------------------------------------------------------
// K0: parameter precompute, thread-parallel (redundant small reductions per
// thread are fine; everything is ~a dozen transcendentals).
// ---------------------------------------------------------------------------
__global__ void k_setup(const float* __restrict__ trans,
                        const float* __restrict__ init,
                        const float* __restrict__ means,
                        const float* __restrict__ logsc)
{
    int tid = threadIdx.x;

    if (tid < 36) {                       // g_logtrans[p][s]
        int p = tid / 6, s = tid - p * 6;
        float m = trans[p * 6 + 0];
#pragma unroll
        for (int k = 1; k < 6; k++) m = fmaxf(m, trans[p * 6 + k]);
        float sum = 0.f;
#pragma unroll
        for (int k = 0; k < 6; k++) sum += expf(trans[p * 6 + k] - m);
        g_logtrans[tid] = logf(expf(trans[p * 6 + s] - m) / sum + 1e-8f);
    }
    if (tid >= 36 && tid < 42) {          // g_loginit[s]
        int s = tid - 36;
        float m = init[0];
#pragma unroll
        for (int k = 1; k < 6; k++) m = fmaxf(m, init[k]);
        float sum = 0.f;
#pragma unroll
        for (int k = 0; k < 6; k++) sum += expf(init[k] - m);
        g_loginit[s] = logf(expf(init[s] - m) / sum + 1e-8f);
    }
    if (tid >= 64 && tid < 136) {         // per-(s,f) inv2 and mu*inv2
        int idx = tid - 64;
        int s = idx / 12, f = idx - s * 12;
        float x    = logsc[s * 12 + f];
        float sc   = log1pf(expf(x)) + 1e-6f;
        float den  = sc + 1e-6f;
        float inv2 = 1.0f / (den * den);
        float mu   = means[s * 12 + f];
        g_epar[s * 12 + f]      = inv2;
        g_epar[72 + s * 12 + f] = mu * inv2;
    }
    if (tid >= 136 && tid < 142) {        // per-s c and logdet
        int s = tid - 136;
        float c = 0.f, ld = 0.f;
#pragma unroll
        for (int f = 0; f < 12; f++) {
            float x    = logsc[s * 12 + f];
            float sc   = log1pf(expf(x)) + 1e-6f;
            float den  = sc + 1e-6f;
            float inv2 = 1.0f / (den * den);
            float mu   = means[s * 12 + f];
            c  += mu * mu * inv2;
            ld += logf(sc);
        }
        g_epar[144 + s] = c;
        g_epar[150 + s] = ld;
    }
}

// ---------------------------------------------------------------------------
// K1: emission logp. 32b x 8t tile; coalesced streaming obs reads and
// coalesced [t][b][s] writes via a padded shared tile.
// ---------------------------------------------------------------------------
#define TILE_PAD 196

__global__ void k_emis(const float* __restrict__ obs)
{
    __shared__ float sp[156];
    __shared__ float tile[8 * TILE_PAD];

    int tid = threadIdx.x;
    if (tid < 156) sp[tid] = g_epar[tid];
    __syncthreads();

    int tt = tid & 7, bb = tid >> 3;
    int t = blockIdx.x * 8 + tt;
    int b = blockIdx.y * 32 + bb;

    const float4* op = (const float4*)(obs + ((size_t)b * NT + t) * NF);
    float4 o0 = __ldcs(op), o1 = __ldcs(op + 1), o2v = __ldcs(op + 2);
    float o[12] = { o0.x, o0.y, o0.z, o0.w, o1.x, o1.y, o1.z, o1.w,
                    o2v.x, o2v.y, o2v.z, o2v.w };
    float osq[12];
#pragma unroll
    for (int f = 0; f < 12; f++) osq[f] = o[f] * o[f];

#pragma unroll
    for (int s = 0; s < NS; s++) {
        float a1 = 0.f, a2 = 0.f;
#pragma unroll
        for (int f = 0; f < 12; f++) {
            a1 = fmaf(osq[f], sp[s * 12 + f], a1);
            a2 = fmaf(o[f],   sp[72 + s * 12 + f], a2);
        }
        float e = -0.5f * (a1 - 2.f * a2 + sp[144 + s]) - sp[150 + s];
        tile[tt * TILE_PAD + bb * 6 + s] = e;
    }
    __syncthreads();

    size_t base = (size_t)(blockIdx.x * 8) * STRIDE + (size_t)blockIdx.y * 32 * NS;
#pragma unroll
    for (int k = 0; k < 6; k++) {
        int idx = k * 256 + tid;
        int tt2 = idx / 192;
        int r   = idx - tt2 * 192;
        g_emis[base + (size_t)tt2 * STRIDE + r] = tile[tt2 * TILE_PAD + r];
    }
}

// ---------------------------------------------------------------------------
// K2: forward Viterbi, VALUES ONLY (no argmax bookkeeping on the serial
// path). 1 thread/batch. Per step: 3 prefetch LDG.64 (depth-8 ring with
// compile-time slots), 36 FADD, 30 FMNMX, 6 FADD, 3 STG.64 of v_t.
// ---------------------------------------------------------------------------
__global__ void k_fwd(float* __restrict__ out, int write_score, int score_off)
{
    int b = blockIdx.x * 32 + threadIdx.x;

    float lt[36];
#pragma unroll
    for (int i = 0; i < 36; i++) lt[i] = g_logtrans[i];

    const float* pe = g_emis + (size_t)b * NS;
    float*       pv = g_v    + (size_t)b * NS;

    float v[6];
#pragma unroll
    for (int s = 0; s < 6; s++) v[s] = g_loginit[s] + pe[s];
    {
        float2* w = (float2*)pv;
        w[0] = make_float2(v[0], v[1]);
        w[1] = make_float2(v[2], v[3]);
        w[2] = make_float2(v[4], v[5]);
    }

    // prefetch ring: slot (t-1)&7 holds e(t)
    float eb[8][6];
#pragma unroll
    for (int k = 0; k < 8; k++) {
        const float2* q = (const float2*)(pe + (size_t)(1 + k) * STRIDE);
        float2 a = __ldcs(q), bq = __ldcs(q + 1), c = __ldcs(q + 2);
        eb[k][0] = a.x; eb[k][1] = a.y; eb[k][2] = bq.x;
        eb[k][3] = bq.y; eb[k][4] = c.x; eb[k][5] = c.y;
    }

    for (int tb = 1; tb < 512; tb += 8) {
#pragma unroll
        for (int u = 0; u < 8; u++) {
            int t = tb + u;
            if (t < 512) {
                float e[6];
#pragma unroll
                for (int s = 0; s < 6; s++) e[s] = eb[u][s];
                // prefetch e(t+8); may land in zero-slack region (never consumed)
                {
                    const float2* q = (const float2*)(pe + (size_t)(t + 8) * STRIDE);
                    float2 a = __ldcs(q), bq = __ldcs(q + 1), c = __ldcs(q + 2);
                    eb[u][0] = a.x; eb[u][1] = a.y; eb[u][2] = bq.x;
                    eb[u][3] = bq.y; eb[u][4] = c.x; eb[u][5] = c.y;
                }
                float nv[6];
#pragma unroll
                for (int s = 0; s < 6; s++) {
                    float m = fmaxf(fmaxf(fmaxf(v[0] + lt[s],      v[1] + lt[6  + s]),
                                          fmaxf(v[2] + lt[12 + s], v[3] + lt[18 + s])),
                                    fmaxf(v[4] + lt[24 + s], v[5] + lt[30 + s]));
                    nv[s] = m + e[s];
                }
#pragma unroll
                for (int s = 0; s < 6; s++) v[s] = nv[s];
                float2* w = (float2*)(pv + (size_t)t * STRIDE);
                w[0] = make_float2(v[0], v[1]);
                w[1] = make_float2(v[2], v[3]);
                w[2] = make_float2(v[4], v[5]);
            }
        }
    }

    // final state / score (first-argmax, strict >)
    float m = v[0]; int idx = 0;
#pragma unroll
    for (int s = 1; s < 6; s++) if (v[s] > m) { m = v[s]; idx = s; }
    g_last[b] = idx;
    if (write_score) out[score_off + b] = m;
}

// ---------------------------------------------------------------------------
// K2b: backpointers, FULLY PARALLEL over (t,b). Each thread recomputes the
// 6 first-argmaxes at one (t,b) site from v_{t-1} and packs 4-bit nibbles.
// Throughput-bound: ~2M independent sites, coalesced 24B reads + 4B writes.
// ---------------------------------------------------------------------------
__global__ void k_bp()
{
    int lane = threadIdx.x & 31;
    int tz   = threadIdx.x >> 5;              // 0..7
    int t    = blockIdx.y * 8 + tz + 1;       // 1..512
    int b    = blockIdx.x * 32 + lane;
    if (t >= 512) return;

    float lt[36];
#pragma unroll
    for (int i = 0; i < 36; i++) lt[i] = g_logtrans[i];

    const float* pv = g_v + (size_t)(t - 1) * STRIDE + (size_t)b * NS;
    float2 a = *(const float2*)pv;
    float2 bb2 = *(const float2*)(pv + 2);
    float2 cc2 = *(const float2*)(pv + 4);
    float v0 = a.x, v1 = a.y, v2 = bb2.x, v3 = bb2.y, v4 = cc2.x, v5 = cc2.y;

    unsigned pk = 0;
#pragma unroll
    for (int s = 0; s < 6; s++) {
        float c0 = v0 + lt[s],      c1 = v1 + lt[6 + s],  c2 = v2 + lt[12 + s];
        float c3 = v3 + lt[18 + s], c4 = v4 + lt[24 + s], c5 = v5 + lt[30 + s];
        // first-argmax tree: later index wins only on strict >
        bool g01 = c1 > c0;  float m01 = g01 ? c1 : c0;  int i01 = g01 ? 1 : 0;
        bool g23 = c3 > c2;  float m23 = g23 ? c3 : c2;  int i23 = g23 ? 3 : 2;
        bool g45 = c5 > c4;  float m45 = g45 ? c5 : c4;  int i45 = g45 ? 5 : 4;
        bool gA  = m23 > m01; float mA = gA ? m23 : m01; int iA  = gA ? i23 : i01;
        bool gB  = m45 > mA;  int idx = gB ? i45 : iA;
        pk |= (unsigned)idx << (4 * s);
    }
    g_bp[(size_t)t * NB + b] = pk;
}

// ---------------------------------------------------------------------------
// K3: backtrace over packed backpointers. ALL ring indices compile-time
// (fully unrolled 32-step blocks, ping-pong register arrays) so buf/nbuf
// live in registers, LDG prefetches issue independently, and the serial
// chain is just SHL+SHF+AND (~12 cyc/step).
// ---------------------------------------------------------------------------
#define BWD_BLOCK(CUR, NXT, DO_PREF)                                        \
do {                                                                        \
    _Pragma("unroll")                                                       \
    for (int i = 0; i < 32; i++) {                                          \
        if (DO_PREF) NXT[i] = __ldg(bprow + (size_t)(tb - 32 - i) * NB);    \
        itile[lane * 33 + 31 - i] = cur;         /* path[tb - i] */         \
        cur = (CUR[i] >> (cur * 4)) & 7;         /* path[tb - i - 1] */     \
    }                                                                       \
    __syncwarp();                                                           \
    if (write_path) {                                                       \
        _Pragma("unroll 8")                                                 \
        for (int r = 0; r < 32; r++)                                        \
            out[(size_t)(b0 + r) * NT + (tb - 31) + lane] =                 \
                (float)itile[r * 33 + lane];                                \
    }                                                                       \
    __syncwarp();                                                           \
    tb -= 32;                                                               \
} while (0)

__global__ void k_bwd(float* __restrict__ out, int write_path)
{
    __shared__ int itile[32 * 33];

    int lane = threadIdx.x;
    int b0 = blockIdx.x * 32;
    int b  = b0 + lane;

    int cur = g_last[b];
    const unsigned* bprow = g_bp + b;

    unsigned buf[32], nbuf[32];
#pragma unroll
    for (int i = 0; i < 32; i++)
        buf[i] = __ldg(bprow + (size_t)(511 - i) * NB);

    int tb = 511;
    for (int blk = 0; blk < 16; blk += 2) {
        BWD_BLOCK(buf,  nbuf, 1);            // blk   (prefetch blk+1, always valid)
        BWD_BLOCK(nbuf, buf,  (blk < 14));   // blk+1 (prefetch blk+2 when it exists)
    }
    // note: last step reads g_bp row 0 (allocated, unused value) — harmless
}

// ---------------------------------------------------------------------------
extern "C" void kernel_launch(void* const* d_in, const int* in_sizes, int n_in,
                              void* d_out, int out_size)
{
    (void)in_sizes; (void)n_in;
    const float* obs  = (const float*)d_in[0];
    const float* tr   = (const float*)d_in[1];
    const float* ini  = (const float*)d_in[2];
    const float* mu   = (const float*)d_in[3];
    const float* lsc  = (const float*)d_in[4];
    float* out = (float*)d_out;

    const int PT = NB * NT;
    int write_path = 0, write_score = 0, score_off = 0;
    if (out_size >= PT + NB)      { write_path = 1; write_score = 1; score_off = PT; }
    else if (out_size >= PT)      { write_path = 1; }
    else                          { write_score = 1; score_off = 0; }

    k_setup<<<1, 160>>>(tr, ini, mu, lsc);
    k_emis<<<dim3(NT / 8, NB / 32), 256>>>(obs);
    k_fwd<<<NB / 32, 32>>>(out, write_score, score_off);
    k_bp<<<dim3(NB / 32, 64), 256>>>();
    k_bwd<<<NB / 32, 32>>>(out, write_path);
}

// round 6
// speedup vs baseline: 2.8288x; 1.8286x over previous
#include <cuda_runtime.h>
#include <math.h>

// Problem dims (fixed by the reference setup)
#define NB 4096
#define NT 512
#define NS 6
#define NF 12
#define NW (NB / 32)          // 128 warps / batch-groups
#define WROW 192              // floats per (warp, t) slice = 32 lanes * 6 states

// Warp-tiled layouts: index(b,t,s) = (b>>5)*SLICES*192 + t*192 + (b&31)*6 + s.
// Consecutive t are 768B apart -> serial kernels stream sequentially.
__device__ float    g_emis[NW * (NT + 8) * WROW];  // 8 slack slices for unguarded prefetch
__device__ float    g_v[NW * NT * WROW];           // Viterbi values
__device__ unsigned g_bp[NW * NT * 32];            // packed backpointers [w][t][lane]
__device__ int      g_last[NB];                    // argmax state at t=511
__device__ float    g_logtrans[NS * NS];           // [p][s]
__device__ float    g_loginit[NS];
__device__ float    g_epar[2 * NS * NF + 2 * NS];  // inv2[72], mu*inv2[72], c[6], logdet[6]

#define EMIS_W ((NT + 8) * WROW)   // per-warp stride in g_emis
#define V_W    (NT * WROW)         // per-warp stride in g_v

// ---------------------------------------------------------------------------
// K0: parameter precompute, thread-parallel.
// ---------------------------------------------------------------------------
__global__ void k_setup(const float* __restrict__ trans,
                        const float* __restrict__ init,
                        const float* __restrict__ means,
                        const float* __restrict__ logsc)
{
    int tid = threadIdx.x;

    if (tid < 36) {                       // g_logtrans[p][s]
        int p = tid / 6, s = tid - p * 6;
        float m = trans[p * 6 + 0];
#pragma unroll
        for (int k = 1; k < 6; k++) m = fmaxf(m, trans[p * 6 + k]);
        float sum = 0.f;
#pragma unroll
        for (int k = 0; k < 6; k++) sum += expf(trans[p * 6 + k] - m);
        g_logtrans[tid] = logf(expf(trans[p * 6 + s] - m) / sum + 1e-8f);
    }
    if (tid >= 36 && tid < 42) {          // g_loginit[s]
        int s = tid - 36;
        float m = init[0];
#pragma unroll
        for (int k = 1; k < 6; k++) m = fmaxf(m, init[k]);
        float sum = 0.f;
#pragma unroll
        for (int k = 0; k < 6; k++) sum += expf(init[k] - m);
        g_loginit[s] = logf(expf(init[s] - m) / sum + 1e-8f);
    }
    if (tid >= 64 && tid < 136) {         // per-(s,f) inv2 and mu*inv2
        int idx = tid - 64;
        int s = idx / 12, f = idx - s * 12;
        float x    = logsc[s * 12 + f];
        float sc   = log1pf(expf(x)) + 1e-6f;
        float den  = sc + 1e-6f;
        float inv2 = 1.0f / (den * den);
        float mu   = means[s * 12 + f];
        g_epar[s * 12 + f]      = inv2;
        g_epar[72 + s * 12 + f] = mu * inv2;
    }
    if (tid >= 136 && tid < 142) {        // per-s c and logdet
        int s = tid - 136;
        float c = 0.f, ld = 0.f;
#pragma unroll
        for (int f = 0; f < 12; f++) {
            float x    = logsc[s * 12 + f];
            float sc   = log1pf(expf(x)) + 1e-6f;
            float den  = sc + 1e-6f;
            float inv2 = 1.0f / (den * den);
            float mu   = means[s * 12 + f];
            c  += mu * mu * inv2;
            ld += logf(sc);
        }
        g_epar[144 + s] = c;
        g_epar[150 + s] = ld;
    }
}

// ---------------------------------------------------------------------------
// K1: emission logp. Block = 32b x 8t tile; coalesced streaming obs reads.
// With the warp-tiled layout, the output tile is ONE contiguous 6144B block:
// dst = g_emis + W*EMIS_W + t0*192 + idx, idx in [0,1536).
// ---------------------------------------------------------------------------
#define TILE_PAD 196

__global__ void k_emis(const float* __restrict__ obs)
{
    __shared__ float sp[156];
    __shared__ float tile[8 * TILE_PAD];

    int tid = threadIdx.x;
    if (tid < 156) sp[tid] = g_epar[tid];
    __syncthreads();

    int tt = tid & 7, bb = tid >> 3;
    int t = blockIdx.x * 8 + tt;
    int b = blockIdx.y * 32 + bb;

    const float4* op = (const float4*)(obs + ((size_t)b * NT + t) * NF);
    float4 o0 = __ldcs(op), o1 = __ldcs(op + 1), o2v = __ldcs(op + 2);
    float o[12] = { o0.x, o0.y, o0.z, o0.w, o1.x, o1.y, o1.z, o1.w,
                    o2v.x, o2v.y, o2v.z, o2v.w };
    float osq[12];
#pragma unroll
    for (int f = 0; f < 12; f++) osq[f] = o[f] * o[f];

#pragma unroll
    for (int s = 0; s < NS; s++) {
        float a1 = 0.f, a2 = 0.f;
#pragma unroll
        for (int f = 0; f < 12; f++) {
            a1 = fmaf(osq[f], sp[s * 12 + f], a1);
            a2 = fmaf(o[f],   sp[72 + s * 12 + f], a2);
        }
        float e = -0.5f * (a1 - 2.f * a2 + sp[144 + s]) - sp[150 + s];
        tile[tt * TILE_PAD + bb * 6 + s] = e;
    }
    __syncthreads();

    float* dst = g_emis + (size_t)blockIdx.y * EMIS_W + (size_t)(blockIdx.x * 8) * WROW;
#pragma unroll
    for (int k = 0; k < 6; k++) {
        int idx = k * 256 + tid;           // 0..1535
        int tt2 = idx / 192;
        int r   = idx - tt2 * 192;
        dst[idx] = tile[tt2 * TILE_PAD + r];
    }
}

// ---------------------------------------------------------------------------
// K2: forward Viterbi, VALUES ONLY. 1 thread/batch, 1 warp/block. Each warp
// streams SEQUENTIALLY through its private 768B-per-step region (read emis,
// write v). Depth-8 compile-time ring; no per-iteration guards (63 full
// 8-blocks for t=1..504, then 7 peeled steps).
// ---------------------------------------------------------------------------
__global__ void __launch_bounds__(32, 1)
k_fwd(float* __restrict__ out, int write_score, int score_off)
{
    int w    = blockIdx.x;
    int lane = threadIdx.x;

    float lt[36];
#pragma unroll
    for (int i = 0; i < 36; i++) lt[i] = g_logtrans[i];

    const float* pe = g_emis + (size_t)w * EMIS_W + lane * 6;
    float*       pv = g_v    + (size_t)w * V_W    + lane * 6;

    float v[6];
#pragma unroll
    for (int s = 0; s < 6; s++) v[s] = g_loginit[s] + pe[s];
    {
        float2* wr = (float2*)pv;
        wr[0] = make_float2(v[0], v[1]);
        wr[1] = make_float2(v[2], v[3]);
        wr[2] = make_float2(v[4], v[5]);
    }

    // ring: slot (t-1)&7 holds e(t); preload t=1..8
    float eb[8][6];
#pragma unroll
    for (int k = 0; k < 8; k++) {
        const float2* q = (const float2*)(pe + (size_t)(1 + k) * WROW);
        float2 a = __ldcs(q), bq = __ldcs(q + 1), c = __ldcs(q + 2);
        eb[k][0] = a.x; eb[k][1] = a.y; eb[k][2] = bq.x;
        eb[k][3] = bq.y; eb[k][4] = c.x; eb[k][5] = c.y;
    }

#define FWD_STEP(T_, U_, PREF_)                                               \
    do {                                                                      \
        float e0 = eb[U_][0], e1 = eb[U_][1], e2 = eb[U_][2];                 \
        float e3 = eb[U_][3], e4 = eb[U_][4], e5 = eb[U_][5];                 \
        if (PREF_) {                                                          \
            const float2* q = (const float2*)(pe + (size_t)((T_) + 8) * WROW);\
            float2 a = __ldcs(q), bq = __ldcs(q + 1), c = __ldcs(q + 2);      \
            eb[U_][0] = a.x; eb[U_][1] = a.y; eb[U_][2] = bq.x;               \
            eb[U_][3] = bq.y; eb[U_][4] = c.x; eb[U_][5] = c.y;               \
        }                                                                     \
        float nv[6];                                                          \
        nv[0] = fmaxf(fmaxf(fmaxf(v[0]+lt[0],  v[1]+lt[6]),                   \
                            fmaxf(v[2]+lt[12], v[3]+lt[18])),                 \
                      fmaxf(v[4]+lt[24], v[5]+lt[30])) + e0;                  \
        nv[1] = fmaxf(fmaxf(fmaxf(v[0]+lt[1],  v[1]+lt[7]),                   \
                            fmaxf(v[2]+lt[13], v[3]+lt[19])),                 \
                      fmaxf(v[4]+lt[25], v[5]+lt[31])) + e1;                  \
        nv[2] = fmaxf(fmaxf(fmaxf(v[0]+lt[2],  v[1]+lt[8]),                   \
                            fmaxf(v[2]+lt[14], v[3]+lt[20])),                 \
                      fmaxf(v[4]+lt[26], v[5]+lt[32])) + e2;                  \
        nv[3] = fmaxf(fmaxf(fmaxf(v[0]+lt[3],  v[1]+lt[9]),                   \
                            fmaxf(v[2]+lt[15], v[3]+lt[21])),                 \
                      fmaxf(v[4]+lt[27], v[5]+lt[33])) + e3;                  \
        nv[4] = fmaxf(fmaxf(fmaxf(v[0]+lt[4],  v[1]+lt[10]),                  \
                            fmaxf(v[2]+lt[16], v[3]+lt[22])),                 \
                      fmaxf(v[4]+lt[28], v[5]+lt[34])) + e4;                  \
        nv[5] = fmaxf(fmaxf(fmaxf(v[0]+lt[5],  v[1]+lt[11]),                  \
                            fmaxf(v[2]+lt[17], v[3]+lt[23])),                 \
                      fmaxf(v[4]+lt[29], v[5]+lt[35])) + e5;                  \
        v[0]=nv[0]; v[1]=nv[1]; v[2]=nv[2]; v[3]=nv[3]; v[4]=nv[4]; v[5]=nv[5];\
        float2* wr = (float2*)(pv + (size_t)(T_) * WROW);                     \
        wr[0] = make_float2(v[0], v[1]);                                      \
        wr[1] = make_float2(v[2], v[3]);                                      \
        wr[2] = make_float2(v[4], v[5]);                                      \
    } while (0)

    for (int tb = 1; tb <= 497; tb += 8) {        // 63 blocks: t = 1..504
#pragma unroll
        for (int u = 0; u < 8; u++) {
            FWD_STEP(tb + u, u, 1);               // prefetch t+8 <= 512 (slack ok)
        }
    }
    // peeled: t = 505..511, slots (t-1)&7 = 0..6, no prefetch
    FWD_STEP(505, 0, 0); FWD_STEP(506, 1, 0); FWD_STEP(507, 2, 0);
    FWD_STEP(508, 3, 0); FWD_STEP(509, 4, 0); FWD_STEP(510, 5, 0);
    FWD_STEP(511, 6, 0);

    // final state / score (first-argmax, strict >)
    float m = v[0]; int idx = 0;
#pragma unroll
    for (int s = 1; s < 6; s++) if (v[s] > m) { m = v[s]; idx = s; }
    int b = w * 32 + lane;
    g_last[b] = idx;
    if (write_score) out[score_off + b] = m;
}

// ---------------------------------------------------------------------------
// K2b: backpointers, fully parallel over (t, b). Reads v_{t-1} (coalesced
// 768B/warp), packs 6 first-argmax nibbles, writes bp[w][t][lane].
// ---------------------------------------------------------------------------
__global__ void k_bp()
{
    int lane = threadIdx.x & 31;
    int tz   = threadIdx.x >> 5;              // 0..7
    int w    = blockIdx.x;
    int t    = blockIdx.y * 8 + tz + 1;       // 1..512
    if (t >= 512) return;

    float lt[36];
#pragma unroll
    for (int i = 0; i < 36; i++) lt[i] = g_logtrans[i];

    const float* pv = g_v + (size_t)w * V_W + (size_t)(t - 1) * WROW + lane * 6;
    float2 a   = *(const float2*)pv;
    float2 bb2 = *(const float2*)(pv + 2);
    float2 cc2 = *(const float2*)(pv + 4);
    float v0 = a.x, v1 = a.y, v2 = bb2.x, v3 = bb2.y, v4 = cc2.x, v5 = cc2.y;

    unsigned pk = 0;
#pragma unroll
    for (int s = 0; s < 6; s++) {
        float c0 = v0 + lt[s],      c1 = v1 + lt[6 + s],  c2 = v2 + lt[12 + s];
        float c3 = v3 + lt[18 + s], c4 = v4 + lt[24 + s], c5 = v5 + lt[30 + s];
        // first-argmax tree: later index wins only on strict >
        bool g01 = c1 > c0;  float m01 = g01 ? c1 : c0;  int i01 = g01 ? 1 : 0;
        bool g23 = c3 > c2;  float m23 = g23 ? c3 : c2;  int i23 = g23 ? 3 : 2;
        bool g45 = c5 > c4;  float m45 = g45 ? c5 : c4;  int i45 = g45 ? 5 : 4;
        bool gA  = m23 > m01; float mA = gA ? m23 : m01; int iA  = gA ? i23 : i01;
        bool gB  = m45 > mA;  int idx = gB ? i45 : iA;
        pk |= (unsigned)idx << (4 * s);
    }
    g_bp[(size_t)w * NT * 32 + (size_t)t * 32 + lane] = pk;
}

// ---------------------------------------------------------------------------
// K3: backtrace. bp stream is now 128B/step CONTIGUOUS per warp. Fully
// unrolled 32-step blocks with ping-pong register buffers (all indices
// compile-time -> registers, independent prefetch LDGs).
// ---------------------------------------------------------------------------
#define BWD_BLOCK(CUR, NXT, DO_PREF)                                        \
do {                                                                        \
    _Pragma("unroll")                                                       \
    for (int i = 0; i < 32; i++) {                                          \
        if (DO_PREF) NXT[i] = __ldg(bprow + (size_t)(tb - 32 - i) * 32);    \
        itile[lane * 33 + 31 - i] = cur;         /* path[tb - i] */         \
        cur = (CUR[i] >> (cur * 4)) & 7;         /* path[tb - i - 1] */     \
    }                                                                       \
    __syncwarp();                                                           \
    if (write_path) {                                                       \
        _Pragma("unroll 8")                                                 \
        for (int r = 0; r < 32; r++)                                        \
            out[(size_t)(b0 + r) * NT + (tb - 31) + lane] =                 \
                (float)itile[r * 33 + lane];                                \
    }                                                                       \
    __syncwarp();                                                           \
    tb -= 32;                                                               \
} while (0)

__global__ void __launch_bounds__(32, 1)
k_bwd(float* __restrict__ out, int write_path)
{
    __shared__ int itile[32 * 33];

    int lane = threadIdx.x;
    int w  = blockIdx.x;
    int b0 = w * 32;

    int cur = g_last[b0 + lane];
    const unsigned* bprow = g_bp + (size_t)w * NT * 32 + lane;

    unsigned buf[32], nbuf[32];
#pragma unroll
    for (int i = 0; i < 32; i++)
        buf[i] = __ldg(bprow + (size_t)(511 - i) * 32);

    int tb = 511;
    for (int blk = 0; blk < 16; blk += 2) {
        BWD_BLOCK(buf,  nbuf, 1);            // prefetch next block (always valid)
        BWD_BLOCK(nbuf, buf,  (blk < 14));
    }
    // note: final step reads bp row 0 (allocated, unused value) — harmless
}

// ---------------------------------------------------------------------------
extern "C" void kernel_launch(void* const* d_in, const int* in_sizes, int n_in,
                              void* d_out, int out_size)
{
    (void)in_sizes; (void)n_in;
    const float* obs  = (const float*)d_in[0];
    const float* tr   = (const float*)d_in[1];
    const float* ini  = (const float*)d_in[2];
    const float* mu   = (const float*)d_in[3];
    const float* lsc  = (const float*)d_in[4];
    float* out = (float*)d_out;

    const int PT = NB * NT;
    int write_path = 0, write_score = 0, score_off = 0;
    if (out_size >= PT + NB)      { write_path = 1; write_score = 1; score_off = PT; }
    else if (out_size >= PT)      { write_path = 1; }
    else                          { write_score = 1; score_off = 0; }

    k_setup<<<1, 160>>>(tr, ini, mu, lsc);
    k_emis<<<dim3(NT / 8, NW), 256>>>(obs);
    k_fwd<<<NW, 32>>>(out, write_score, score_off);
    k_bp<<<dim3(NW, 64), 256>>>();
    k_bwd<<<NW, 32>>>(out, write_path);
}